// round 11
// baseline (speedup 1.0000x reference)
#include <cuda_runtime.h>
#include <math.h>
#include <stdint.h>
#include <cuda_fp16.h>

#define L_ 256
#define C_ 128
#define G_ 4
#define P_ 32
#define R_ (L_*L_)   // 65536 rows

// Scratch (allocation-free device globals, 16B-aligned for vector access)
static __device__ __align__(16) __half d_qh [R_*C_];
static __device__ __align__(16) __half d_kh [R_*C_];
static __device__ __align__(16) __half d_vTh[R_*C_];   // [g][c][i][k]
static __device__ __align__(16) __half d_gth[R_*C_];
static __device__ __align__(16) __half d_oh [R_*C_];
static __device__ __align__(16) __half d_bTh[(size_t)G_*R_];  // [g][k][j]
static __device__ __align__(16) __half d_WTh [512*128];  // fused [Wq*qs|Wk|Wv|Wg]^T [n][k]
static __device__ __align__(16) __half d_WoTh[128*128];  // Wo^T [n][k]

__device__ __forceinline__ float sigmoidf_(float x){ return 1.f/(1.f+__expf(-x)); }

__device__ __forceinline__ void mma_f16(float* d, const uint32_t* a, const uint32_t* b){
    asm volatile("mma.sync.aligned.m16n8k16.row.col.f32.f16.f16.f32 "
        "{%0,%1,%2,%3}, {%4,%5,%6,%7}, {%8,%9}, {%0,%1,%2,%3};"
        : "+f"(d[0]),"+f"(d[1]),"+f"(d[2]),"+f"(d[3])
        : "r"(a[0]),"r"(a[1]),"r"(a[2]),"r"(a[3]), "r"(b[0]),"r"(b[1]));
}

// ---------------------------------------------------------------------------
// Prep: W^T fp16 [n][k]; fold 1/sqrt(P) into WqT.
// ---------------------------------------------------------------------------
__global__ void prep_kernel(const float* __restrict__ Wq, const float* __restrict__ Wk,
                            const float* __restrict__ Wv, const float* __restrict__ Wg,
                            const float* __restrict__ Wo)
{
    int n = blockIdx.x, k = threadIdx.x;
    if (n < 512){
        int m = n>>7, c = n&127;
        const float* W = (m==0)?Wq:(m==1)?Wk:(m==2)?Wv:Wg;
        float w = W[k*C_ + c];
        if (m==0) w *= 0.17677669529663687f;   // 1/sqrt(32)
        d_WTh[n*C_ + k] = __float2half(w);
    } else {
        int c = n - 512;
        d_WoTh[c*C_ + k] = __float2half(Wo[k*C_ + c]);
    }
}

// ---------------------------------------------------------------------------
// Bias: d_bTh[g][k][j] = x[j*L+k,:] . Wb[:,g]  (fp32 math, fp16 store)
// ---------------------------------------------------------------------------
__global__ void __launch_bounds__(256) bias_kernel(const float* __restrict__ x,
                                                   const float* __restrict__ Wb)
{
    __shared__ float4 sWb[128];
    int tid = threadIdx.x;
    if (tid < 128)
        sWb[tid] = make_float4(Wb[tid*4+0], Wb[tid*4+1], Wb[tid*4+2], Wb[tid*4+3]);
    __syncthreads();
    int r = blockIdx.x*256 + tid;
    const float4* xr = (const float4*)(x + (size_t)r*C_);
    float a0=0.f,a1=0.f,a2=0.f,a3=0.f;
    #pragma unroll 8
    for (int c4=0;c4<32;c4++){
        float4 xv = xr[c4];
        float4 w0 = sWb[c4*4+0], w1 = sWb[c4*4+1], w2 = sWb[c4*4+2], w3 = sWb[c4*4+3];
        a0 = fmaf(xv.x,w0.x,a0); a1 = fmaf(xv.x,w0.y,a1); a2 = fmaf(xv.x,w0.z,a2); a3 = fmaf(xv.x,w0.w,a3);
        a0 = fmaf(xv.y,w1.x,a0); a1 = fmaf(xv.y,w1.y,a1); a2 = fmaf(xv.y,w1.z,a2); a3 = fmaf(xv.y,w1.w,a3);
        a0 = fmaf(xv.z,w2.x,a0); a1 = fmaf(xv.z,w2.y,a1); a2 = fmaf(xv.z,w2.z,a2); a3 = fmaf(xv.z,w2.w,a3);
        a0 = fmaf(xv.w,w3.x,a0); a1 = fmaf(xv.w,w3.y,a1); a2 = fmaf(xv.w,w3.z,a2); a3 = fmaf(xv.w,w3.w,a3);
    }
    int kk = r & (L_-1), jj = r >> 8;
    d_bTh[(size_t)0*R_ + kk*L_ + jj] = __float2half(a0);
    d_bTh[(size_t)1*R_ + kk*L_ + jj] = __float2half(a1);
    d_bTh[(size_t)2*R_ + kk*L_ + jj] = __float2half(a2);
    d_bTh[(size_t)3*R_ + kk*L_ + jj] = __float2half(a3);
}

// ---------------------------------------------------------------------------
// Proj via mma m16n8k16 fp16. CTA: 128 rows x 128 cols, full K=128 staged.
// Grid (512, 4): by = matrix (0:q 1:k 2:v 3:gate). V written transposed.
// smem rows: 136 halves (68 words): banks 4r+t4 conflict-free.
// ---------------------------------------------------------------------------
#define PADH 136
#define GEMM_SMEM (2*128*PADH*2)   // 69632 B

__global__ void __launch_bounds__(256,2) proj_kernel(
    const float* __restrict__ x, const float* __restrict__ bg)
{
    extern __shared__ __half smh[];
    __half* sA = smh;                // [128][136]
    __half* sB = smh + 128*PADH;     // [128][136]

    const int tid = threadIdx.x, wid = tid>>5, lane = tid&31;
    const int warp_m = wid & 3, warp_n = wid >> 2;
    const int g4 = lane>>2, t4 = lane&3;
    const int rbase = blockIdx.x * 128;
    const int mat   = blockIdx.y;
    const int cbase = mat * 128;

    // stage A: x fp32 -> fp16
    #pragma unroll 4
    for (int i=tid; i<4096; i+=256){
        int row = i>>5, k4 = i&31;
        float4 v = ((const float4*)x)[(size_t)(rbase+row)*32 + k4];
        __half2* d = (__half2*)sA + row*(PADH/2) + k4*2;
        d[0] = __floats2half2_rn(v.x, v.y);
        d[1] = __floats2half2_rn(v.z, v.w);
    }
    // stage B: d_WTh copy
    #pragma unroll 4
    for (int i=tid; i<2048; i+=256){
        int row = i>>4, seg = i&15;
        ((uint4*)sB)[row*17 + seg] = ((const uint4*)d_WTh)[(size_t)(cbase+row)*16 + seg];
    }
    __syncthreads();

    float acc[2][8][4];
    #pragma unroll
    for (int mt=0;mt<2;mt++)
        #pragma unroll
        for (int nt=0;nt<8;nt++)
            #pragma unroll
            for (int e=0;e<4;e++) acc[mt][nt][e]=0.f;

    const uint32_t* sAw = (const uint32_t*)sA;
    const uint32_t* sBw = (const uint32_t*)sB;

    #pragma unroll
    for (int ks=0; ks<8; ks++){
        uint32_t a[2][4];
        #pragma unroll
        for (int mt=0;mt<2;mt++){
            int w = (warp_m*32 + mt*16 + g4)*(PADH/2) + ks*8 + t4;
            a[mt][0]=sAw[w]; a[mt][1]=sAw[w+8*(PADH/2)];
            a[mt][2]=sAw[w+4]; a[mt][3]=sAw[w+8*(PADH/2)+4];
        }
        #pragma unroll
        for (int nt=0;nt<8;nt++){
            int w = (warp_n*64 + nt*8 + g4)*(PADH/2) + ks*8 + t4;
            uint32_t b[2] = { sBw[w], sBw[w+4] };
            mma_f16(acc[0][nt], a[0], b);
            mma_f16(acc[1][nt], a[1], b);
        }
    }

    // epilogue
    #pragma unroll
    for (int mt=0;mt<2;mt++){
        #pragma unroll
        for (int half=0;half<2;half++){
            const int row = rbase + warp_m*32 + mt*16 + g4 + half*8;
            #pragma unroll
            for (int nt=0;nt<8;nt++){
                const int col = warp_n*64 + nt*8 + t4*2;   // mat-local 0..127
                float v0 = acc[mt][nt][half*2+0], v1 = acc[mt][nt][half*2+1];
                if (mat==0){
                    *(__half2*)(d_qh + (size_t)row*C_ + col) = __floats2half2_rn(v0,v1);
                } else if (mat==1){
                    *(__half2*)(d_kh + (size_t)row*C_ + col) = __floats2half2_rn(v0,v1);
                } else if (mat==3){
                    v0 = sigmoidf_(v0 + bg[col]); v1 = sigmoidf_(v1 + bg[col+1]);
                    *(__half2*)(d_gth + (size_t)row*C_ + col) = __floats2half2_rn(v0,v1);
                } else {
                    // V transposed: d_vTh[((g*32+c)*256 + i)*256 + k]
                    int g = col>>5, c = col&31;
                    int ii = row>>8, kk = row&255;
                    d_vTh[((size_t)(g*32+c  )*256 + ii)*256 + kk] = __float2half(v0);
                    d_vTh[((size_t)(g*32+c+1)*256 + ii)*256 + kk] = __float2half(v1);
                }
            }
        }
    }
}

// ---------------------------------------------------------------------------
// Attention, full fp16 mma. One CTA per (i,g). 8 warps, 64-key chunks.
// No-max softmax. sK[64][40]h, sVT[32][72]h (transposed V), sST[256][72]h
// ([j][k] E for PV A), sSum[64][9] f32.
// ---------------------------------------------------------------------------
#define SKH  0
#define SVTH (64*40)                 // 2560
#define SSTH (SVTH + 32*72)          // 4864
#define SUMH (SSTH + 256*72)         // 23296 (halves)
#define ATTN_SMEM (SUMH*2 + 64*9*4)  // 46592 + 2304 = 48896 B

__global__ void __launch_bounds__(256,2) attn_kernel()
{
    extern __shared__ __half smh[];
    __half* sK   = smh + SKH;
    __half* sVT  = smh + SVTH;
    __half* sST  = smh + SSTH;
    float*  sSum = (float*)(smh + SUMH);

    const int tid = threadIdx.x, wid = tid>>5, lane = tid&31;
    const int g4 = lane>>2, t4 = lane&3;
    const int bi = blockIdx.x >> 2;
    const int g  = blockIdx.x & 3;
    const int jb = wid * 32;

    // Q fragments from global fp16 (B operand of QK mma)
    uint32_t qb[4][2][2];
    {
        #pragma unroll
        for (int nt=0;nt<4;nt++){
            const uint32_t* qw = (const uint32_t*)d_qh
                + (size_t)(bi*L_ + jb + nt*8 + g4)*(C_/2) + g*16;
            qb[nt][0][0] = qw[t4];      qb[nt][0][1] = qw[t4+4];
            qb[nt][1][0] = qw[t4+8];    qb[nt][1][1] = qw[t4+12];
        }
    }

    float oacc[2][4][4];
    #pragma unroll
    for (int mt=0;mt<2;mt++)
        #pragma unroll
        for (int nt=0;nt<4;nt++)
            #pragma unroll
            for (int e=0;e<4;e++) oacc[mt][nt][e]=0.f;

    const __half* biasg = d_bTh + (size_t)g*R_;

    for (int kt=0; kt<4; kt++){
        const int k0 = kt*64;
        __syncthreads();
        {   // stage K [64][32] (uint4 copy)
            int row = tid>>2, seg = tid&3;
            ((uint4*)sK)[row*5 + seg] =
                ((const uint4*)d_kh)[(size_t)(bi*L_ + k0 + row)*16 + g*4 + seg];
            // stage V^T [32][64] (uint4 copy from d_vTh)
            int c = tid>>3, s2 = tid&7;
            ((uint4*)sVT)[c*9 + s2] =
                ((const uint4*)d_vTh)[((size_t)(g*32+c)*256 + bi)*32 + kt*8 + s2];
        }
        __syncthreads();

        // ---- QK: S^T[k][j] via fp16 mma; exp on fragments; [j][k] store ----
        const uint32_t* sKw = (const uint32_t*)sK;
        #pragma unroll
        for (int h=0; h<2; h++){
            float sacc[2][4][4];
            #pragma unroll
            for (int mt=0;mt<2;mt++)
                #pragma unroll
                for (int nt=0;nt<4;nt++){
                    const __half* bp = biasg + (size_t)(k0 + h*32 + mt*16 + g4)*L_ + jb + nt*8 + 2*t4;
                    float2 lo = __half22float2(*(const __half2*)bp);
                    float2 hi = __half22float2(*(const __half2*)(bp + 8*L_));
                    sacc[mt][nt][0]=lo.x; sacc[mt][nt][1]=lo.y;
                    sacc[mt][nt][2]=hi.x; sacc[mt][nt][3]=hi.y;
                }
            #pragma unroll
            for (int ks=0; ks<2; ks++){
                uint32_t a[2][4];
                #pragma unroll
                for (int mt=0;mt<2;mt++){
                    int w = (h*32 + mt*16 + g4)*20 + ks*8 + t4;
                    a[mt][0]=sKw[w]; a[mt][1]=sKw[w+8*20];
                    a[mt][2]=sKw[w+4]; a[mt][3]=sKw[w+8*20+4];
                }
                #pragma unroll
                for (int mt=0;mt<2;mt++)
                    #pragma unroll
                    for (int nt=0;nt<4;nt++)
                        mma_f16(sacc[mt][nt], a[mt], qb[nt][ks]);
            }
            // exp, transposed store [j][k], per-k partial sums
            #pragma unroll
            for (int mt=0;mt<2;mt++){
                const int rA = h*32 + mt*16 + g4;
                float sumA = 0.f, sumB = 0.f;
                #pragma unroll
                for (int nt=0;nt<4;nt++){
                    const int col = jb + nt*8 + 2*t4;
                    float e0 = __expf(sacc[mt][nt][0]);
                    float e1 = __expf(sacc[mt][nt][1]);
                    float e2 = __expf(sacc[mt][nt][2]);
                    float e3 = __expf(sacc[mt][nt][3]);
                    sumA += e0 + e1;
                    sumB += e2 + e3;
                    sST[(col  )*72 + rA    ] = __float2half(e0);
                    sST[(col+1)*72 + rA    ] = __float2half(e1);
                    sST[(col  )*72 + rA + 8] = __float2half(e2);
                    sST[(col+1)*72 + rA + 8] = __float2half(e3);
                }
                sumA += __shfl_xor_sync(0xffffffffu, sumA, 1);
                sumA += __shfl_xor_sync(0xffffffffu, sumA, 2);
                sumB += __shfl_xor_sync(0xffffffffu, sumB, 1);
                sumB += __shfl_xor_sync(0xffffffffu, sumB, 2);
                if (t4 == 0){
                    sSum[rA*9 + wid]     = sumA;
                    sSum[(rA+8)*9 + wid] = sumB;
                }
            }
        }
        __syncthreads();

        // ---- fold 1/sum into V^T: thread handles k=tid&63, 8 c's ----
        {
            const int k = tid & 63, cq = (tid >> 6) * 8;
            float s = 0.f;
            #pragma unroll
            for (int w=0; w<8; w++) s += sSum[k*9 + w];
            const float inv = __frcp_rn(s);
            #pragma unroll
            for (int c=0; c<8; c++){
                __half* vp = sVT + (cq+c)*72 + k;
                *vp = __float2half(__half2float(*vp) * inv);
            }
        }
        __syncthreads();

        // ---- PV: O[j][c] += E[j][k] * V^T[c][k], fp16 mma, K=64 ----
        const uint32_t* sSw = (const uint32_t*)sST;
        const uint32_t* sVw = (const uint32_t*)sVT;
        #pragma unroll
        for (int ks=0; ks<4; ks++){
            uint32_t a[2][4], b[4][2];
            #pragma unroll
            for (int mt=0;mt<2;mt++){
                int w = (jb + mt*16 + g4)*36 + ks*8 + t4;
                a[mt][0]=sSw[w]; a[mt][1]=sSw[w+8*36];
                a[mt][2]=sSw[w+4]; a[mt][3]=sSw[w+8*36+4];
            }
            #pragma unroll
            for (int nt=0;nt<4;nt++){
                int w = (nt*8 + g4)*36 + ks*8 + t4;
                b[nt][0]=sVw[w]; b[nt][1]=sVw[w+4];
            }
            #pragma unroll
            for (int mt=0;mt<2;mt++)
                #pragma unroll
                for (int nt=0;nt<4;nt++)
                    mma_f16(oacc[mt][nt], a[mt], b[nt]);
        }
    }

    // ---- epilogue: gate (fp16) mul + fp16 store ----
    #pragma unroll
    for (int mt=0;mt<2;mt++)
        #pragma unroll
        for (int half=0;half<2;half++){
            const int j = jb + mt*16 + g4 + half*8;
            #pragma unroll
            for (int nt=0;nt<4;nt++){
                const int c = nt*8 + 2*t4;
                size_t ga = (size_t)(bi*L_ + j)*C_ + g*P_ + c;
                float2 gt = __half22float2(*(const __half2*)(d_gth + ga));
                float v0 = oacc[mt][nt][half*2+0]*gt.x;
                float v1 = oacc[mt][nt][half*2+1]*gt.y;
                *(__half2*)(d_oh + ga) = __floats2half2_rn(v0, v1);
            }
        }
}

// ---------------------------------------------------------------------------
// Out-proj fp16 mma: out = d_oh @ Wo + bo (fp32 out)
// ---------------------------------------------------------------------------
__global__ void __launch_bounds__(256,2) outproj_kernel(
    const float* __restrict__ bo, float* __restrict__ out)
{
    extern __shared__ __half smh[];
    __half* sA = smh;
    __half* sB = smh + 128*PADH;

    const int tid = threadIdx.x, wid = tid>>5, lane = tid&31;
    const int warp_m = wid & 3, warp_n = wid >> 2;
    const int g4 = lane>>2, t4 = lane&3;
    const int rbase = blockIdx.x * 128;

    #pragma unroll 4
    for (int i=tid; i<2048; i+=256){
        int row = i>>4, seg = i&15;
        ((uint4*)sA)[row*17 + seg] = ((const uint4*)d_oh)[(size_t)(rbase+row)*16 + seg];
        ((uint4*)sB)[row*17 + seg] = ((const uint4*)d_WoTh)[(size_t)row*16 + seg];
    }
    __syncthreads();

    float acc[2][8][4];
    #pragma unroll
    for (int mt=0;mt<2;mt++)
        #pragma unroll
        for (int nt=0;nt<8;nt++)
            #pragma unroll
            for (int e=0;e<4;e++) acc[mt][nt][e]=0.f;

    const uint32_t* sAw = (const uint32_t*)sA;
    const uint32_t* sBw = (const uint32_t*)sB;

    #pragma unroll
    for (int ks=0; ks<8; ks++){
        uint32_t a[2][4];
        #pragma unroll
        for (int mt=0;mt<2;mt++){
            int w = (warp_m*32 + mt*16 + g4)*(PADH/2) + ks*8 + t4;
            a[mt][0]=sAw[w]; a[mt][1]=sAw[w+8*(PADH/2)];
            a[mt][2]=sAw[w+4]; a[mt][3]=sAw[w+8*(PADH/2)+4];
        }
        #pragma unroll
        for (int nt=0;nt<8;nt++){
            int w = (warp_n*64 + nt*8 + g4)*(PADH/2) + ks*8 + t4;
            uint32_t b[2] = { sBw[w], sBw[w+4] };
            mma_f16(acc[0][nt], a[0], b);
            mma_f16(acc[1][nt], a[1], b);
        }
    }

    #pragma unroll
    for (int mt=0;mt<2;mt++){
        #pragma unroll
        for (int half=0;half<2;half++){
            const int row = rbase + warp_m*32 + mt*16 + g4 + half*8;
            #pragma unroll
            for (int nt=0;nt<8;nt++){
                const int col = warp_n*64 + nt*8 + t4*2;
                float v0 = acc[mt][nt][half*2+0] + bo[col];
                float v1 = acc[mt][nt][half*2+1] + bo[col+1];
                *(float2*)(out + (size_t)row*C_ + col) = make_float2(v0, v1);
            }
        }
    }
}

// ---------------------------------------------------------------------------
extern "C" void kernel_launch(void* const* d_in, const int* in_sizes, int n_in,
                              void* d_out, int out_size)
{
    const float* x  = (const float*)d_in[0];
    const float* Wq = (const float*)d_in[1];
    const float* Wk = (const float*)d_in[2];
    const float* Wv = (const float*)d_in[3];
    const float* Wb = (const float*)d_in[4];
    const float* Wg = (const float*)d_in[5];
    const float* bg = (const float*)d_in[6];
    const float* Wo = (const float*)d_in[7];
    const float* bo = (const float*)d_in[8];
    float* out = (float*)d_out;

    cudaFuncSetAttribute(proj_kernel,
                         cudaFuncAttributeMaxDynamicSharedMemorySize, GEMM_SMEM);
    cudaFuncSetAttribute(attn_kernel,
                         cudaFuncAttributeMaxDynamicSharedMemorySize, ATTN_SMEM);
    cudaFuncSetAttribute(outproj_kernel,
                         cudaFuncAttributeMaxDynamicSharedMemorySize, GEMM_SMEM);

    prep_kernel<<<640, 128>>>(Wq, Wk, Wv, Wg, Wo);
    bias_kernel<<<256, 256>>>(x, Wb);
    proj_kernel<<<dim3(R_/128, 4), 256, GEMM_SMEM>>>(x, bg);
    attn_kernel<<<L_*G_, 256, ATTN_SMEM>>>();
    outproj_kernel<<<R_/128, 256, GEMM_SMEM>>>(bo, out);
}